// round 6
// baseline (speedup 1.0000x reference)
#include <cuda_runtime.h>

// ScatterLoss — per-class contrastive hinge loss.
// d_in[0] = output [N, D] float32 (N=65536, D=512)
// d_in[1] = label_id [N] int32
// out     = scalar float32
//
// loss = (1/N) * sum_k cnt_k * relu(1 - || s_k/c_k - (T - s_k)/(N - c_k) + 1e-6 ||_2)^2

#define NCLS 512
#define DDIM 512
#define NF4  (DDIM / 4)   // 128 float4 columns
#define CAP  1024         // max rows per class (counts ~128±11)
#define NSPL 4            // class split factor for the streaming kernel

// Zeroed each replay by a single 4KB memset node (0 bits == 0.0f).
struct ZeroBlk { int cnt[NCLS]; float d2[NCLS]; };
static __device__ ZeroBlk g_z;

static __device__ int   g_idx[NCLS * CAP];
static __device__ float g_sumsp[NSPL][NCLS][DDIM];   // per-quarter class sums

// ---------------------------------------------------------------------------
// K1: counting-sort scatter — per-class row-index lists.
// ---------------------------------------------------------------------------
__global__ void k_scatter(const int* __restrict__ lab, int N)
{
    int i = blockIdx.x * blockDim.x + threadIdx.x;
    if (i < N) {
        int k = lab[i];
        if (k >= 0 && k < NCLS) {
            int pos = atomicAdd(&g_z.cnt[k], 1);
            if (pos < CAP) g_idx[k * CAP + pos] = i;
        }
    }
}

// ---------------------------------------------------------------------------
// K2: per-class partial sums. Four CTAs per class (contiguous quarters of the
// row list) -> 2048 CTAs, ~32 rows each, deep MLP on the 2KB coalesced row
// reads. Reads the full 128 MB matrix exactly once -> HBM bound.
// ---------------------------------------------------------------------------
__global__ void __launch_bounds__(128) k_class_sum_q(const float* __restrict__ out)
{
    __shared__ int srows[CAP / NSPL + NSPL];

    int k  = blockIdx.x >> 2;
    int h  = blockIdx.x & 3;
    int nk = min(g_z.cnt[k], CAP);
    int j0 = (h * nk) >> 2;
    int j1 = ((h + 1) * nk) >> 2;
    int nj = j1 - j0;

    for (int j = threadIdx.x; j < nj; j += blockDim.x)
        srows[j] = g_idx[k * CAP + j0 + j];
    __syncthreads();

    int q = threadIdx.x;  // float4 column 0..127

    float4 acc = make_float4(0.f, 0.f, 0.f, 0.f);
    #pragma unroll 8
    for (int j = 0; j < nj; j++) {
        const float4* row = (const float4*)(out + (size_t)srows[j] * DDIM);
        float4 v = __ldg(row + q);
        acc.x += v.x; acc.y += v.y; acc.z += v.z; acc.w += v.w;
    }
    ((float4*)g_sumsp[h][k])[q] = acc;
}

// ---------------------------------------------------------------------------
// K3: fused grand-total + per-class distance partials.
// One CTA per float4 column (128 CTAs x 128 threads). Thread t folds classes
// {t, t+128, t+256, t+384} across the 4 quarters (16 L2-resident float4
// loads), the block tree-reduces to T[col], then each thread emits its 4
// classes' 4-dim contribution to d2_k with one spread atomicAdd each.
// ---------------------------------------------------------------------------
__global__ void __launch_bounds__(128) k_colloss(float fN)
{
    __shared__ float4 red[128];
    int cg = blockIdx.x;   // float4 column
    int t  = threadIdx.x;

    float4 s[4];
    float4 T = make_float4(0.f, 0.f, 0.f, 0.f);
    #pragma unroll
    for (int j = 0; j < 4; j++) {
        int k = t + j * 128;
        float4 a = make_float4(0.f, 0.f, 0.f, 0.f);
        #pragma unroll
        for (int h = 0; h < NSPL; h++) {
            float4 v = ((const float4*)g_sumsp[h][k])[cg];
            a.x += v.x; a.y += v.y; a.z += v.z; a.w += v.w;
        }
        s[j] = a;
        T.x += a.x; T.y += a.y; T.z += a.z; T.w += a.w;
    }

    red[t] = T;
    __syncthreads();
    #pragma unroll
    for (int sh = 64; sh > 0; sh >>= 1) {
        if (t < sh) {
            float4 b = red[t + sh];
            red[t].x += b.x; red[t].y += b.y; red[t].z += b.z; red[t].w += b.w;
        }
        __syncthreads();
    }
    T = red[0];

    #pragma unroll
    for (int j = 0; j < 4; j++) {
        int k = t + j * 128;
        int c = g_z.cnt[k];
        if (c > 0) {
            float fc  = (float)c;
            float ip  = 1.f / fc;
            float in_ = 1.f / (fN - fc);
            float dx = s[j].x * ip - (T.x - s[j].x) * in_ + 1e-6f;
            float dy = s[j].y * ip - (T.y - s[j].y) * in_ + 1e-6f;
            float dz = s[j].z * ip - (T.z - s[j].z) * in_ + 1e-6f;
            float dw = s[j].w * ip - (T.w - s[j].w) * in_ + 1e-6f;
            float p = dx * dx + dy * dy + dz * dz + dw * dw;
            atomicAdd(&g_z.d2[k], p);
        }
    }
}

// ---------------------------------------------------------------------------
// K4: final — per-class hinge, count-weighted mean over N. 1 CTA x 512 thr.
// ---------------------------------------------------------------------------
__global__ void __launch_bounds__(NCLS) k_final(float* __restrict__ out, float fN)
{
    __shared__ float red[NCLS];
    int k = threadIdx.x;
    int c = g_z.cnt[k];

    float w = 0.f;
    if (c > 0) {
        float dist = sqrtf(g_z.d2[k]);
        float m = fmaxf(1.0f - dist, 0.f);   // MARGIN = 1.0
        w = (float)c * m * m;
    }
    red[k] = w;
    __syncthreads();
    #pragma unroll
    for (int s = NCLS / 2; s > 0; s >>= 1) {
        if (k < s) red[k] += red[k + s];
        __syncthreads();
    }
    if (k == 0) out[0] = red[0] / fN;
}

// ---------------------------------------------------------------------------
extern "C" void kernel_launch(void* const* d_in, const int* in_sizes, int n_in,
                              void* d_out, int out_size)
{
    const float* output = (const float*)d_in[0];
    const int*   label  = (const int*)d_in[1];
    int N = in_sizes[1];

    void* zptr = nullptr;
    cudaGetSymbolAddress(&zptr, g_z);            // not a stream op; capture-safe
    cudaMemsetAsync(zptr, 0, sizeof(ZeroBlk));   // zero counters + d2 partials

    k_scatter<<<(N + 255) / 256, 256>>>(label, N);
    k_class_sum_q<<<NCLS * NSPL, 128>>>(output);
    k_colloss<<<NF4, 128>>>((float)N);
    k_final<<<1, NCLS>>>((float*)d_out, (float)N);
}

// round 7
// speedup vs baseline: 1.1208x; 1.1208x over previous
#include <cuda_runtime.h>

// ScatterLoss — per-class contrastive hinge loss.
// d_in[0] = output [N, D] float32 (N=65536, D=512)
// d_in[1] = label_id [N] int32
// out     = scalar float32
//
// loss = (1/N) * sum_k cnt_k * relu(1 - || s_k/c_k - (T - s_k)/(N - c_k) + 1e-6 ||_2)^2

#define NCLS 512
#define DDIM 512
#define NF4  (DDIM / 4)   // 128 float4 columns
#define CAP  1024         // max rows per class (counts ~128±11)
#define NSPL 4            // class split factor for the streaming kernel
#define PAD  32           // ints per 128B line — atomic-target padding

// Zeroed each replay by one memset node (0 bits == 0.0f == 0).
// cnt/d2 padded: one counter per 128B L2 line -> atomics spread over all
// L2 partitions instead of 16 lines.
struct ZeroBlk {
    int   cnt[NCLS * PAD];
    float d2[NCLS * PAD];
    unsigned int ticket;
};
static __device__ ZeroBlk g_z;

static __device__ int   g_idx[NCLS * CAP];
static __device__ float g_sumsp[NSPL][NCLS][DDIM];   // per-quarter class sums

// ---------------------------------------------------------------------------
// K1: counting-sort scatter — per-class row-index lists. Padded counters.
// ---------------------------------------------------------------------------
__global__ void k_scatter(const int* __restrict__ lab, int N)
{
    int i = blockIdx.x * blockDim.x + threadIdx.x;
    if (i < N) {
        int k = lab[i];
        if (k >= 0 && k < NCLS) {
            int pos = atomicAdd(&g_z.cnt[k * PAD], 1);
            if (pos < CAP) g_idx[k * CAP + pos] = i;
        }
    }
}

// ---------------------------------------------------------------------------
// K2: per-class partial sums. Four CTAs per class (contiguous quarters of
// the row list). Index words are loaded warp-uniform (hardware broadcast) —
// no smem staging, no syncs. 2KB coalesced row reads, unroll 8 for MLP.
// Reads the full 128 MB matrix exactly once -> HBM bound (dominant kernel).
// ---------------------------------------------------------------------------
__global__ void __launch_bounds__(128) k_class_sum_q(const float* __restrict__ out)
{
    int k  = blockIdx.x >> 2;
    int h  = blockIdx.x & 3;
    int nk = min(g_z.cnt[k * PAD], CAP);
    int j0 = (h * nk) >> 2;
    int j1 = ((h + 1) * nk) >> 2;
    int nj = j1 - j0;

    const int* idx = g_idx + k * CAP + j0;
    int q = threadIdx.x;  // float4 column 0..127

    float4 acc = make_float4(0.f, 0.f, 0.f, 0.f);
    #pragma unroll 8
    for (int j = 0; j < nj; j++) {
        int r = __ldg(idx + j);                       // uniform -> broadcast
        const float4* row = (const float4*)(out + (size_t)r * DDIM);
        float4 v = __ldg(row + q);
        acc.x += v.x; acc.y += v.y; acc.z += v.z; acc.w += v.w;
    }
    ((float4*)g_sumsp[h][k])[q] = acc;
}

// ---------------------------------------------------------------------------
// K3: fused grand-total + per-class distance partials + (last CTA) finalize.
// One CTA per float4 column (128 CTAs x 128 threads). Thread t folds classes
// {t, t+128, t+256, t+384} across the 4 quarters (16 L2-resident float4
// loads), block tree-reduces to T[col], each thread deposits its 4 classes'
// 4-dim d^2 contribution (padded atomics). The last CTA to finish performs
// the hinge + count-weighted mean and writes the scalar output.
// ---------------------------------------------------------------------------
__global__ void __launch_bounds__(128) k_colloss(float* __restrict__ outp, float fN)
{
    __shared__ float4 red[128];
    __shared__ unsigned int s_tkt;
    int cg = blockIdx.x;   // float4 column
    int t  = threadIdx.x;

    float4 s[4];
    float4 T = make_float4(0.f, 0.f, 0.f, 0.f);
    #pragma unroll
    for (int j = 0; j < 4; j++) {
        int k = t + j * 128;
        float4 a = make_float4(0.f, 0.f, 0.f, 0.f);
        #pragma unroll
        for (int h = 0; h < NSPL; h++) {
            float4 v = ((const float4*)g_sumsp[h][k])[cg];
            a.x += v.x; a.y += v.y; a.z += v.z; a.w += v.w;
        }
        s[j] = a;
        T.x += a.x; T.y += a.y; T.z += a.z; T.w += a.w;
    }

    red[t] = T;
    __syncthreads();
    #pragma unroll
    for (int sh = 64; sh > 0; sh >>= 1) {
        if (t < sh) {
            float4 b = red[t + sh];
            red[t].x += b.x; red[t].y += b.y; red[t].z += b.z; red[t].w += b.w;
        }
        __syncthreads();
    }
    T = red[0];

    #pragma unroll
    for (int j = 0; j < 4; j++) {
        int k = t + j * 128;
        int c = g_z.cnt[k * PAD];
        if (c > 0) {
            float fc  = (float)c;
            float ip  = 1.f / fc;
            float in_ = 1.f / (fN - fc);
            float dx = s[j].x * ip - (T.x - s[j].x) * in_ + 1e-6f;
            float dy = s[j].y * ip - (T.y - s[j].y) * in_ + 1e-6f;
            float dz = s[j].z * ip - (T.z - s[j].z) * in_ + 1e-6f;
            float dw = s[j].w * ip - (T.w - s[j].w) * in_ + 1e-6f;
            float p = dx * dx + dy * dy + dz * dz + dw * dw;
            atomicAdd(&g_z.d2[k * PAD], p);
        }
    }

    // --- last-CTA finalize ---
    __threadfence();
    __syncthreads();
    if (t == 0) s_tkt = atomicAdd(&g_z.ticket, 1u);
    __syncthreads();
    if (s_tkt == (unsigned)(gridDim.x - 1)) {
        // all other CTAs' d2 deposits are visible (fence before ticket).
        float w = 0.f;
        #pragma unroll
        for (int j = 0; j < 4; j++) {
            int k = t + j * 128;
            int c = g_z.cnt[k * PAD];
            if (c > 0) {
                float dist = sqrtf(g_z.d2[k * PAD]);
                float m = fmaxf(1.0f - dist, 0.f);   // MARGIN = 1.0
                w += (float)c * m * m;
            }
        }
        // block reduce 128 partials
        ((float*)red)[t] = w;
        __syncthreads();
        #pragma unroll
        for (int sh = 64; sh > 0; sh >>= 1) {
            if (t < sh) ((float*)red)[t] += ((float*)red)[t + sh];
            __syncthreads();
        }
        if (t == 0) outp[0] = ((float*)red)[0] / fN;
    }
}

// ---------------------------------------------------------------------------
extern "C" void kernel_launch(void* const* d_in, const int* in_sizes, int n_in,
                              void* d_out, int out_size)
{
    const float* output = (const float*)d_in[0];
    const int*   label  = (const int*)d_in[1];
    int N = in_sizes[1];

    void* zptr = nullptr;
    cudaGetSymbolAddress(&zptr, g_z);            // host-side query; capture-safe
    cudaMemsetAsync(zptr, 0, sizeof(ZeroBlk));   // counters + d2 + ticket

    k_scatter<<<(N + 255) / 256, 256>>>(label, N);
    k_class_sum_q<<<NCLS * NSPL, 128>>>(output);
    k_colloss<<<NF4, 128>>>((float*)d_out, (float)N);
}